// round 9
// baseline (speedup 1.0000x reference)
#include <cuda_runtime.h>
#include <cuda_bf16.h>

#define BB_ 64
#define LL_ 2048

typedef unsigned long long ull;
typedef unsigned int u32;

// Ping-pong buffers for the tree levels.
__device__ float g_bufA[BB_ * LL_ * 128];        // 67 MB
__device__ float g_bufB[BB_ * (LL_ / 2) * 128];  // 33.5 MB
// Permuted split W_hh: [chunk(4)][n(160)][k(128)] bf16, n = gate*32 + within-chunk col
__device__ __align__(16) __nv_bfloat16 g_Whi[4 * 160 * 128];
__device__ __align__(16) __nv_bfloat16 g_Wlo[4 * 160 * 128];
// Split W_wh transposed: [n(128)][k(128)]
__device__ __align__(16) __nv_bfloat16 g_Ehi[128 * 128];
__device__ __align__(16) __nv_bfloat16 g_Elo[128 * 128];

extern __shared__ float smem[];

// ---------------- scalar helpers ----------------
__device__ __forceinline__ float tanhfast(float x) {
    float y; asm("tanh.approx.f32 %0, %1;" : "=f"(y) : "f"(x)); return y;
}
__device__ __forceinline__ float sig_fast(float x) {
    return fmaf(0.5f, tanhfast(0.5f * x), 0.5f);
}
__device__ __forceinline__ float tanh_f(float x) {
    return 1.0f - 2.0f / (__expf(2.0f * x) + 1.0f);
}

// Truncation split of 4 floats -> packed bf16 hi (2x u32) + rn bf16 lo (2x u32).
__device__ __forceinline__ void split4(const float* v, uint2& hi_st, uint2& lo_st) {
    u32 b0 = __float_as_uint(v[0]), b1 = __float_as_uint(v[1]);
    u32 b2 = __float_as_uint(v[2]), b3 = __float_as_uint(v[3]);
    hi_st.x = __byte_perm(b0, b1, 0x7632);
    hi_st.y = __byte_perm(b2, b3, 0x7632);
    float h0 = __uint_as_float(b0 & 0xFFFF0000u);
    float h1 = __uint_as_float(b1 & 0xFFFF0000u);
    float h2 = __uint_as_float(b2 & 0xFFFF0000u);
    float h3 = __uint_as_float(b3 & 0xFFFF0000u);
    __nv_bfloat162 l01 = __floats2bfloat162_rn(v[0] - h0, v[1] - h1);
    __nv_bfloat162 l23 = __floats2bfloat162_rn(v[2] - h2, v[3] - h3);
    lo_st.x = *(u32*)&l01;
    lo_st.y = *(u32*)&l23;
}

// ---------------- cp.async ----------------
__device__ __forceinline__ void cp16(void* s, const void* g) {
    unsigned a = (unsigned)__cvta_generic_to_shared(s);
    asm volatile("cp.async.cg.shared.global [%0], [%1], 16;" :: "r"(a), "l"(g));
}
#define CP_COMMIT() asm volatile("cp.async.commit_group;")
#define CP_WAIT0()  asm volatile("cp.async.wait_group 0;")

// ---------------- mma.sync helpers ----------------
__device__ __forceinline__ u32 smem_u32(const void* p) {
    u32 a;
    asm("{ .reg .u64 t; cvta.to.shared.u64 t, %1; cvt.u32.u64 %0, t; }" : "=r"(a) : "l"(p));
    return a;
}
__device__ __forceinline__ void ldsm4(u32* r, u32 saddr) {
    asm volatile("ldmatrix.sync.aligned.m8n8.x4.shared.b16 {%0,%1,%2,%3}, [%4];"
                 : "=r"(r[0]), "=r"(r[1]), "=r"(r[2]), "=r"(r[3]) : "r"(saddr));
}
__device__ __forceinline__ void ldsm2(u32* r, u32 saddr) {
    asm volatile("ldmatrix.sync.aligned.m8n8.x2.shared.b16 {%0,%1}, [%2];"
                 : "=r"(r[0]), "=r"(r[1]) : "r"(saddr));
}
__device__ __forceinline__ void mma16816(float* d, const u32* a, u32 b0, u32 b1) {
    asm volatile(
        "mma.sync.aligned.m16n8k16.row.col.f32.bf16.bf16.f32 "
        "{%0,%1,%2,%3}, {%4,%5,%6,%7}, {%8,%9}, {%0,%1,%2,%3};"
        : "+f"(d[0]), "+f"(d[1]), "+f"(d[2]), "+f"(d[3])
        : "r"(a[0]), "r"(a[1]), "r"(a[2]), "r"(a[3]), "r"(b0), "r"(b1));
}

// =====================================================================
// Prep kernels: split weights to bf16 hi/lo (exact rn split, done once).
// =====================================================================
__global__ void prep_w(const float* __restrict__ Whh) {
    int idx = blockIdx.x * 256 + threadIdx.x;  // over 128*640
    if (idx >= 128 * 640) return;
    int k = idx / 640, col = idx - k * 640;
    int g = col >> 7, c = col & 127;
    int chunk = c >> 5, cl = c & 31;
    int n = g * 32 + cl;
    float w = Whh[idx];
    __nv_bfloat16 hi = __float2bfloat16_rn(w);
    __nv_bfloat16 lo = __float2bfloat16_rn(w - __bfloat162float(hi));
    int dst = (chunk * 160 + n) * 128 + k;
    g_Whi[dst] = hi;
    g_Wlo[dst] = lo;
}
__global__ void prep_e(const float* __restrict__ Wwh) {
    int idx = blockIdx.x * 256 + threadIdx.x;  // over 128*128
    if (idx >= 128 * 128) return;
    int k = idx >> 7, n = idx & 127;
    float w = Wwh[idx];
    __nv_bfloat16 hi = __float2bfloat16_rn(w);
    __nv_bfloat16 lo = __float2bfloat16_rn(w - __bfloat162float(hi));
    g_Ehi[n * 128 + k] = hi;
    g_Elo[n * 128 + k] = lo;
}

// =====================================================================
// PERSISTENT embed: h0 = emb[ids] @ W_wh. W-split resident in smem,
// CTA loops over M=64 gather tiles. 256 thr, 8 warps (2x4), warp 32x32.
// smem: Ahi 16K | Alo 16K | Bhi 32K | Blo 32K = 96KB -> 2 CTAs/SM.
// =====================================================================
__global__ __launch_bounds__(256, 2) void embed_pers(const int* __restrict__ ids,
                                                     const float* __restrict__ emb,
                                                     int ntiles) {
    char* sm = (char*)smem;
    int t = threadIdx.x;

    // B fill once via cp.async.
    for (int j = t; j < 2 * 128 * 16; j += 256) {
        int split = j >> 11, rem = j & 2047;
        int row = rem >> 4, q = rem & 15;
        const __nv_bfloat16* src = split ? g_Elo : g_Ehi;
        u32 kpb = (u32)(4 * q) ^ ((row & 7) << 2);
        cp16(sm + 32768 + split * 32768 + (row * 64 + kpb) * 4, &src[row * 128 + q * 8]);
    }
    CP_COMMIT();

    u32 smb = smem_u32(sm);
    int lane = t & 31, warp = t >> 5;
    int wm = warp >> 2, wn = warp & 3;
    int t8 = lane >> 3, l7 = lane & 7;
    u32 xsw = (u32)(l7 << 2);
    int arow = wm * 32 + (t8 & 1) * 8 + l7;
    u32 tka = (u32)((t8 >> 1) * 4);
    int brow = wn * 32 + (t8 >> 1) * 8 + l7;
    u32 tkb = (u32)((t8 & 1) * 4);
    int grp = lane >> 2, tid4 = lane & 3;

    for (int tile = blockIdx.x; tile < ntiles; tile += gridDim.x) {
        int r0 = tile * 64;
        __syncthreads();  // previous tile MMA done before A overwrite

        // A: gather + truncation split. Fully unrolled -> batched LDGs.
#pragma unroll
        for (int ii = 0; ii < 8; ii++) {
            int i = t + ii * 256;
            int rr = i >> 5, c4 = i & 31;
            int id = ids[r0 + rr];
            float4 v = ((const float4*)emb)[(long long)id * 32 + c4];
            float xv[4] = {v.x, v.y, v.z, v.w};
            uint2 hi_st, lo_st;
            split4(xv, hi_st, lo_st);
            u32 sw = (u32)(2 * c4) ^ ((rr & 7) << 2);
            *(uint2*)(sm + (rr * 64 + sw) * 4) = hi_st;
            *(uint2*)(sm + 16384 + (rr * 64 + sw) * 4) = lo_st;
        }
        CP_WAIT0();  // B ready (no-op after first tile)
        __syncthreads();

        float acc[2][4][4];
#pragma unroll
        for (int a = 0; a < 2; a++)
#pragma unroll
            for (int b = 0; b < 4; b++)
#pragma unroll
                for (int c = 0; c < 4; c++) acc[a][b][c] = 0.0f;

#pragma unroll 1
        for (int ks = 0; ks < 8; ks++) {
#pragma unroll
            for (int split = 0; split < 3; split++) {
                u32 abase = smb + ((split == 2) ? 16384u : 0u);
                u32 bbase = smb + 32768u + ((split == 1) ? 32768u : 0u);
                u32 ka = (((u32)(ks * 8) + tka) ^ xsw) * 4;
                u32 kb = (((u32)(ks * 8) + tkb) ^ xsw) * 4;
                u32 af[2][4];
                ldsm4(af[0], abase + (u32)arow * 256 + ka);
                ldsm4(af[1], abase + (u32)(arow + 16) * 256 + ka);
#pragma unroll
                for (int np = 0; np < 2; np++) {
                    u32 bf[4];
                    ldsm4(bf, bbase + (u32)(brow + np * 16) * 256 + kb);
                    mma16816(acc[0][2 * np], af[0], bf[0], bf[1]);
                    mma16816(acc[0][2 * np + 1], af[0], bf[2], bf[3]);
                    mma16816(acc[1][2 * np], af[1], bf[0], bf[1]);
                    mma16816(acc[1][2 * np + 1], af[1], bf[2], bf[3]);
                }
            }
        }

#pragma unroll
        for (int mf = 0; mf < 2; mf++)
#pragma unroll
            for (int nf = 0; nf < 4; nf++) {
                int row = r0 + wm * 32 + mf * 16 + grp;
                int col = wn * 32 + nf * 8 + tid4 * 2;
                *(float2*)&g_bufA[(long long)row * 128 + col] =
                    make_float2(acc[mf][nf][0], acc[mf][nf][1]);
                *(float2*)&g_bufA[(long long)(row + 8) * 128 + col] =
                    make_float2(acc[mf][nf][2], acc[mf][nf][3]);
            }
    }
}

// =====================================================================
// Persistent tree-level kernel, 2 CTAs/SM. Grid (<=74, 4 chunks).
// CTA = M=64 rows x N=160 (5 gates x 32 cols), 256 thr, 8 warps (2m x 4n).
// smem: A 2x16KB | B 2x40KB | bias 640B = 115328 B -> 2 CTAs/SM.
// =====================================================================
#define QB_ALO 16384
#define QB_B 32768
#define QB_BIAS 114688
#define QB_SM 115328

__global__ __launch_bounds__(256, 2) void combine_q(int src_sel,
                                                    float* __restrict__ out_param,
                                                    int dst_sel,
                                                    const float* __restrict__ bhh,
                                                    int lg_nhalf, int ntiles) {
    char* sm = (char*)smem;
    int t = threadIdx.x;
    int chunk = blockIdx.y;
    int n_half = 1 << lg_nhalf;

    const float* hin = (src_sel == 0) ? g_bufA : g_bufB;
    float* hout = (dst_sel == 0) ? g_bufA : (dst_sel == 1) ? g_bufB : out_param;

    // B fill once via cp.async: [split(2)][row 160][16 uint4], swizzled.
    for (int j = t; j < 2 * 160 * 16; j += 256) {
        int split = j / 2560, rem = j - split * 2560;
        int row = rem >> 4, q = rem & 15;
        const __nv_bfloat16* src = split ? g_Wlo : g_Whi;
        u32 kpb = (u32)(4 * q) ^ ((row & 7) << 2);
        cp16(sm + QB_B + split * 40960 + (row * 64 + kpb) * 4,
             &src[(chunk * 160 + row) * 128 + q * 8]);
    }
    CP_COMMIT();
    float* bias_s = (float*)(sm + QB_BIAS);
    for (int j = t; j < 160; j += 256)
        bias_s[j] = 2.0f * bhh[(j >> 5) * 128 + chunk * 32 + (j & 31)];

    u32 smb = smem_u32(sm);
    int lane = t & 31, warp = t >> 5;
    int wm = warp >> 2, wn = warp & 3;  // 2 x 4
    int t8 = lane >> 3, l7 = lane & 7;
    u32 xsw = (u32)(l7 << 2);
    int arow = wm * 32 + (t8 & 1) * 8 + l7;
    u32 tka = (u32)((t8 >> 1) * 4);
    int rowB = wn * 8 + l7;
    int bgsel = t8 >> 1;
    u32 tkb = (u32)((t8 & 1) * 4);
    int grp = lane >> 2, tid4 = lane & 3;
    int cl = wn * 8 + tid4 * 2;
    int hcol = chunk * 32 + cl;

    const float4* hin4 = (const float4*)hin;

    for (int tile = blockIdx.x; tile < ntiles; tile += gridDim.x) {
        int r0 = tile * 64;
        __syncthreads();  // previous tile's MMA done before A overwrite

        // A fill: x = hl + hr, truncation split, swizzled. Fully unrolled.
#pragma unroll
        for (int ii = 0; ii < 8; ii++) {
            int i = t + ii * 256;
            int rr = i >> 5, c4 = i & 31;
            int r = r0 + rr;
            int b = r >> lg_nhalf;
            int iw = r - (b << lg_nhalf);
            long long base = (long long)b * (2 * n_half);
            float4 l4 = hin4[(base + 2 * iw) * 32 + c4];
            float4 r4 = hin4[(base + 2 * iw + 1) * 32 + c4];
            float xv[4] = {l4.x + r4.x, l4.y + r4.y, l4.z + r4.z, l4.w + r4.w};
            uint2 hi_st, lo_st;
            split4(xv, hi_st, lo_st);
            u32 sw = (u32)(2 * c4) ^ ((rr & 7) << 2);
            *(uint2*)(sm + (rr * 64 + sw) * 4) = hi_st;
            *(uint2*)(sm + QB_ALO + (rr * 64 + sw) * 4) = lo_st;
        }

        // Prefetch epilogue operands (latency drains behind the MMA loop).
        float2 hl_pre[2][2], hr_pre[2][2];
#pragma unroll
        for (int mf = 0; mf < 2; mf++)
#pragma unroll
            for (int half = 0; half < 2; half++) {
                int rr = wm * 32 + mf * 16 + grp + half * 8;
                int r = r0 + rr;
                int b = r >> lg_nhalf;
                int iw = r - (b << lg_nhalf);
                long long rowL = (long long)b * (2 * n_half) + 2 * iw;
                hl_pre[mf][half] = *(const float2*)&hin[rowL * 128 + hcol];
                hr_pre[mf][half] = *(const float2*)&hin[(rowL + 1) * 128 + hcol];
            }

        CP_WAIT0();  // B ready (no-op after first tile)
        __syncthreads();

        float acc[2][5][4];
#pragma unroll
        for (int a = 0; a < 2; a++)
#pragma unroll
            for (int g = 0; g < 5; g++)
#pragma unroll
                for (int c = 0; c < 4; c++) acc[a][g][c] = 0.0f;

#pragma unroll 1
        for (int ks = 0; ks < 8; ks++) {
#pragma unroll
            for (int split = 0; split < 3; split++) {
                u32 abase = smb + ((split == 2) ? (u32)QB_ALO : 0u);
                u32 bbase = smb + QB_B + ((split == 1) ? 40960u : 0u);
                u32 ka = (((u32)(ks * 8) + tka) ^ xsw) * 4;
                u32 kb = (((u32)(ks * 8) + tkb) ^ xsw) * 4;
                u32 af[2][4];
                ldsm4(af[0], abase + (u32)arow * 256 + ka);
                ldsm4(af[1], abase + (u32)(arow + 16) * 256 + ka);
                u32 b01[4], b23[4], b4[2];
                ldsm4(b01, bbase + (u32)((0 + bgsel) * 32 + rowB) * 256 + kb);
                ldsm4(b23, bbase + (u32)((2 + bgsel) * 32 + rowB) * 256 + kb);
                ldsm2(b4, bbase + (u32)(4 * 32 + rowB) * 256 + kb);
                mma16816(acc[0][0], af[0], b01[0], b01[1]);
                mma16816(acc[1][0], af[1], b01[0], b01[1]);
                mma16816(acc[0][1], af[0], b01[2], b01[3]);
                mma16816(acc[1][1], af[1], b01[2], b01[3]);
                mma16816(acc[0][2], af[0], b23[0], b23[1]);
                mma16816(acc[1][2], af[1], b23[0], b23[1]);
                mma16816(acc[0][3], af[0], b23[2], b23[3]);
                mma16816(acc[1][3], af[1], b23[2], b23[3]);
                mma16816(acc[0][4], af[0], b4[0], b4[1]);
                mma16816(acc[1][4], af[1], b4[0], b4[1]);
            }
        }

        // Epilogue: gates + hl/hr already in registers.
#pragma unroll
        for (int mf = 0; mf < 2; mf++) {
#pragma unroll
            for (int half = 0; half < 2; half++) {
                int rr = wm * 32 + mf * 16 + grp + half * 8;
                int r = r0 + rr;
                float hl2[2] = {hl_pre[mf][half].x, hl_pre[mf][half].y};
                float hr2[2] = {hr_pre[mf][half].x, hr_pre[mf][half].y};
                float ov[2];
#pragma unroll
                for (int j = 0; j < 2; j++) {
                    int e = half * 2 + j;
                    float si = acc[mf][0][e] + bias_s[0 * 32 + cl + j];
                    float sl = acc[mf][1][e] + bias_s[1 * 32 + cl + j];
                    float sr = acc[mf][2][e] + bias_s[2 * 32 + cl + j];
                    float so = acc[mf][3][e] + bias_s[3 * 32 + cl + j];
                    float sg = acc[mf][4][e] + bias_s[4 * 32 + cl + j];
                    float cc = sig_fast(si) * tanh_f(sg) + sig_fast(sl) * hl2[j] +
                               sig_fast(sr) * hr2[j];
                    ov[j] = sig_fast(so) * tanh_f(cc);
                }
                *(float2*)&hout[(long long)r * 128 + hcol] = make_float2(ov[0], ov[1]);
            }
        }
    }
}

// ---------------- launcher ----------------
extern "C" void kernel_launch(void* const* d_in, const int* in_sizes, int n_in,
                              void* d_out, int out_size) {
    const int* ids = (const int*)d_in[0];
    const float* emb = (const float*)d_in[1];
    const float* Wwh = (const float*)d_in[2];
    const float* Whh = (const float*)d_in[3];
    const float* bhh = (const float*)d_in[4];
    float* out = (float*)d_out;

    const int smem_embed = 98304;
    cudaFuncSetAttribute(embed_pers, cudaFuncAttributeMaxDynamicSharedMemorySize, smem_embed);
    cudaFuncSetAttribute(combine_q, cudaFuncAttributeMaxDynamicSharedMemorySize, QB_SM);

    prep_w<<<(128 * 640 + 255) / 256, 256>>>(Whh);
    prep_e<<<(128 * 128 + 255) / 256, 256>>>(Wwh);

    {
        int ntiles = (BB_ * LL_) / 64;  // 2048
        int gx = ntiles < 296 ? ntiles : 296;
        embed_pers<<<gx, 256, smem_embed>>>(ids, emb, ntiles);
    }

    for (int tlev = 1; tlev <= 11; ++tlev) {
        int ntiles = (BB_ * (LL_ >> tlev)) / 64;  // M=64 tiles
        int lg = 11 - tlev;
        int src_sel = (tlev & 1) ? 0 : 1;
        int dst_sel = (tlev == 11) ? 2 : ((tlev & 1) ? 1 : 0);
        int gx = ntiles < 74 ? ntiles : 74;
        dim3 grid(gx, 4);
        combine_q<<<grid, 256, QB_SM>>>(src_sel, out, dst_sel, bhh, lg, ntiles);
    }
}

// round 10
// speedup vs baseline: 1.0525x; 1.0525x over previous
#include <cuda_runtime.h>
#include <cuda_bf16.h>

#define BB_ 64
#define LL_ 2048

typedef unsigned long long ull;
typedef unsigned int u32;

// Ping-pong buffers for the tree levels.
__device__ float g_bufA[BB_ * LL_ * 128];        // 67 MB
__device__ float g_bufB[BB_ * (LL_ / 2) * 128];  // 33.5 MB
// Permuted split W_hh: [chunk(4)][n(160)][k(128)] bf16, n = gate*32 + within-chunk col
__device__ __align__(16) __nv_bfloat16 g_Whi[4 * 160 * 128];
__device__ __align__(16) __nv_bfloat16 g_Wlo[4 * 160 * 128];
// Split W_wh transposed: [n(128)][k(128)]
__device__ __align__(16) __nv_bfloat16 g_Ehi[128 * 128];
__device__ __align__(16) __nv_bfloat16 g_Elo[128 * 128];

extern __shared__ float smem[];

// ---------------- scalar helpers ----------------
__device__ __forceinline__ float tanhfast(float x) {
    float y; asm("tanh.approx.f32 %0, %1;" : "=f"(y) : "f"(x)); return y;
}
__device__ __forceinline__ float sig_fast(float x) {
    return fmaf(0.5f, tanhfast(0.5f * x), 0.5f);
}
__device__ __forceinline__ float tanh_f(float x) {
    return 1.0f - 2.0f / (__expf(2.0f * x) + 1.0f);
}

// ---------------- cp.async ----------------
__device__ __forceinline__ void cp16(void* s, const void* g) {
    unsigned a = (unsigned)__cvta_generic_to_shared(s);
    asm volatile("cp.async.cg.shared.global [%0], [%1], 16;" :: "r"(a), "l"(g));
}
#define CP_COMMIT() asm volatile("cp.async.commit_group;")
#define CP_WAIT0()  asm volatile("cp.async.wait_group 0;")

// ---------------- mma.sync helpers ----------------
__device__ __forceinline__ u32 smem_u32(const void* p) {
    u32 a;
    asm("{ .reg .u64 t; cvta.to.shared.u64 t, %1; cvt.u32.u64 %0, t; }" : "=r"(a) : "l"(p));
    return a;
}
__device__ __forceinline__ void ldsm4(u32* r, u32 saddr) {
    asm volatile("ldmatrix.sync.aligned.m8n8.x4.shared.b16 {%0,%1,%2,%3}, [%4];"
                 : "=r"(r[0]), "=r"(r[1]), "=r"(r[2]), "=r"(r[3]) : "r"(saddr));
}
__device__ __forceinline__ void ldsm2(u32* r, u32 saddr) {
    asm volatile("ldmatrix.sync.aligned.m8n8.x2.shared.b16 {%0,%1}, [%2];"
                 : "=r"(r[0]), "=r"(r[1]) : "r"(saddr));
}
__device__ __forceinline__ void mma16816(float* d, const u32* a, u32 b0, u32 b1) {
    asm volatile(
        "mma.sync.aligned.m16n8k16.row.col.f32.bf16.bf16.f32 "
        "{%0,%1,%2,%3}, {%4,%5,%6,%7}, {%8,%9}, {%0,%1,%2,%3};"
        : "+f"(d[0]), "+f"(d[1]), "+f"(d[2]), "+f"(d[3])
        : "r"(a[0]), "r"(a[1]), "r"(a[2]), "r"(a[3]), "r"(b0), "r"(b1));
}

// =====================================================================
// Prep (single launch): split W_hh and W_wh to bf16 hi/lo.
// =====================================================================
__global__ void prep_both(const float* __restrict__ Whh, const float* __restrict__ Wwh) {
    int idx = blockIdx.x * 256 + threadIdx.x;
    if (idx < 128 * 640) {
        int k = idx / 640, col = idx - k * 640;
        int g = col >> 7, c = col & 127;
        int chunk = c >> 5, cl = c & 31;
        int n = g * 32 + cl;
        float w = Whh[idx];
        __nv_bfloat16 hi = __float2bfloat16_rn(w);
        __nv_bfloat16 lo = __float2bfloat16_rn(w - __bfloat162float(hi));
        int dst = (chunk * 160 + n) * 128 + k;
        g_Whi[dst] = hi;
        g_Wlo[dst] = lo;
    } else if (idx < 128 * 640 + 128 * 128) {
        int e = idx - 128 * 640;
        int k = e >> 7, n = e & 127;
        float w = Wwh[e];
        __nv_bfloat16 hi = __float2bfloat16_rn(w);
        __nv_bfloat16 lo = __float2bfloat16_rn(w - __bfloat162float(hi));
        g_Ehi[n * 128 + k] = hi;
        g_Elo[n * 128 + k] = lo;
    }
}

// =====================================================================
// PERSISTENT embed: h0 = emb[ids] @ W_wh. W-split resident in smem,
// CTA loops over M=64 gather tiles. 256 thr, 8 warps (2x4), warp 32x32.
// smem: Ahi 16K | Alo 16K | Bhi 32K | Blo 32K = 96KB -> 2 CTAs/SM.
// =====================================================================
__global__ __launch_bounds__(256, 2) void embed_pers(const int* __restrict__ ids,
                                                     const float* __restrict__ emb,
                                                     int ntiles) {
    char* sm = (char*)smem;
    int t = threadIdx.x;

    // B fill once via cp.async.
    for (int j = t; j < 2 * 128 * 16; j += 256) {
        int split = j >> 11, rem = j & 2047;
        int row = rem >> 4, q = rem & 15;
        const __nv_bfloat16* src = split ? g_Elo : g_Ehi;
        u32 kpb = (u32)(4 * q) ^ ((row & 7) << 2);
        cp16(sm + 32768 + split * 32768 + (row * 64 + kpb) * 4, &src[row * 128 + q * 8]);
    }
    CP_COMMIT();

    u32 smb = smem_u32(sm);
    int lane = t & 31, warp = t >> 5;
    int wm = warp >> 2, wn = warp & 3;
    int t8 = lane >> 3, l7 = lane & 7;
    u32 xsw = (u32)(l7 << 2);
    int arow = wm * 32 + (t8 & 1) * 8 + l7;
    u32 tka = (u32)((t8 >> 1) * 4);
    int brow = wn * 32 + (t8 >> 1) * 8 + l7;
    u32 tkb = (u32)((t8 & 1) * 4);
    int grp = lane >> 2, tid4 = lane & 3;

    for (int tile = blockIdx.x; tile < ntiles; tile += gridDim.x) {
        int r0 = tile * 64;
        __syncthreads();  // previous tile MMA done before A overwrite

        // A: gather + split (rolled loop -> moderate MLP, no L1tex pileup).
        for (int i = t; i < 64 * 32; i += 256) {
            int rr = i >> 5, c4 = i & 31;
            int id = ids[r0 + rr];
            float4 v = ((const float4*)emb)[(long long)id * 32 + c4];
            float xv[4] = {v.x, v.y, v.z, v.w};
            __nv_bfloat16 hi[4], lo[4];
#pragma unroll
            for (int j = 0; j < 4; j++) {
                hi[j] = __float2bfloat16_rn(xv[j]);
                lo[j] = __float2bfloat16_rn(xv[j] - __bfloat162float(hi[j]));
            }
            u32 sw = (u32)(2 * c4) ^ ((rr & 7) << 2);
            *(uint2*)(sm + (rr * 64 + sw) * 4) = *(uint2*)hi;
            *(uint2*)(sm + 16384 + (rr * 64 + sw) * 4) = *(uint2*)lo;
        }
        CP_WAIT0();  // B ready (no-op after first tile)
        __syncthreads();

        float acc[2][4][4];
#pragma unroll
        for (int a = 0; a < 2; a++)
#pragma unroll
            for (int b = 0; b < 4; b++)
#pragma unroll
                for (int c = 0; c < 4; c++) acc[a][b][c] = 0.0f;

#pragma unroll 1
        for (int ks = 0; ks < 8; ks++) {
#pragma unroll
            for (int split = 0; split < 3; split++) {
                u32 abase = smb + ((split == 2) ? 16384u : 0u);
                u32 bbase = smb + 32768u + ((split == 1) ? 32768u : 0u);
                u32 ka = (((u32)(ks * 8) + tka) ^ xsw) * 4;
                u32 kb = (((u32)(ks * 8) + tkb) ^ xsw) * 4;
                u32 af[2][4];
                ldsm4(af[0], abase + (u32)arow * 256 + ka);
                ldsm4(af[1], abase + (u32)(arow + 16) * 256 + ka);
#pragma unroll
                for (int np = 0; np < 2; np++) {
                    u32 bf[4];
                    ldsm4(bf, bbase + (u32)(brow + np * 16) * 256 + kb);
                    mma16816(acc[0][2 * np], af[0], bf[0], bf[1]);
                    mma16816(acc[0][2 * np + 1], af[0], bf[2], bf[3]);
                    mma16816(acc[1][2 * np], af[1], bf[0], bf[1]);
                    mma16816(acc[1][2 * np + 1], af[1], bf[2], bf[3]);
                }
            }
        }

#pragma unroll
        for (int mf = 0; mf < 2; mf++)
#pragma unroll
            for (int nf = 0; nf < 4; nf++) {
                int row = r0 + wm * 32 + mf * 16 + grp;
                int col = wn * 32 + nf * 8 + tid4 * 2;
                *(float2*)&g_bufA[(long long)row * 128 + col] =
                    make_float2(acc[mf][nf][0], acc[mf][nf][1]);
                *(float2*)&g_bufA[(long long)(row + 8) * 128 + col] =
                    make_float2(acc[mf][nf][2], acc[mf][nf][3]);
            }
    }
}

// =====================================================================
// Persistent tree-level kernel, 2 CTAs/SM. Grid (<=74, 4 chunks).
// CTA = M=64 rows x N=160 (5 gates x 32 cols), 256 thr, 8 warps (2m x 4n).
// Epilogue hl/hr prefetched into registers before the MMA loop.
// smem: A 2x16KB | B 2x40KB | bias 640B = 115328 B -> 2 CTAs/SM.
// =====================================================================
#define QB_ALO 16384
#define QB_B 32768
#define QB_BIAS 114688
#define QB_SM 115328

__global__ __launch_bounds__(256, 2) void combine_q(int src_sel,
                                                    float* __restrict__ out_param,
                                                    int dst_sel,
                                                    const float* __restrict__ bhh,
                                                    int lg_nhalf, int ntiles) {
    char* sm = (char*)smem;
    int t = threadIdx.x;
    int chunk = blockIdx.y;
    int n_half = 1 << lg_nhalf;

    const float* hin = (src_sel == 0) ? g_bufA : g_bufB;
    float* hout = (dst_sel == 0) ? g_bufA : (dst_sel == 1) ? g_bufB : out_param;

    // B fill once via cp.async: [split(2)][row 160][16 uint4], swizzled.
    for (int j = t; j < 2 * 160 * 16; j += 256) {
        int split = j / 2560, rem = j - split * 2560;
        int row = rem >> 4, q = rem & 15;
        const __nv_bfloat16* src = split ? g_Wlo : g_Whi;
        u32 kpb = (u32)(4 * q) ^ ((row & 7) << 2);
        cp16(sm + QB_B + split * 40960 + (row * 64 + kpb) * 4,
             &src[(chunk * 160 + row) * 128 + q * 8]);
    }
    CP_COMMIT();
    float* bias_s = (float*)(sm + QB_BIAS);
    for (int j = t; j < 160; j += 256)
        bias_s[j] = 2.0f * bhh[(j >> 5) * 128 + chunk * 32 + (j & 31)];

    u32 smb = smem_u32(sm);
    int lane = t & 31, warp = t >> 5;
    int wm = warp >> 2, wn = warp & 3;  // 2 x 4
    int t8 = lane >> 3, l7 = lane & 7;
    u32 xsw = (u32)(l7 << 2);
    int arow = wm * 32 + (t8 & 1) * 8 + l7;
    u32 tka = (u32)((t8 >> 1) * 4);
    int rowB = wn * 8 + l7;
    int bgsel = t8 >> 1;
    u32 tkb = (u32)((t8 & 1) * 4);
    int grp = lane >> 2, tid4 = lane & 3;
    int cl = wn * 8 + tid4 * 2;
    int hcol = chunk * 32 + cl;

    const float4* hin4 = (const float4*)hin;

    for (int tile = blockIdx.x; tile < ntiles; tile += gridDim.x) {
        int r0 = tile * 64;
        __syncthreads();  // previous tile's MMA done before A overwrite

        // A fill: x = hl + hr, rn split, swizzled (rolled loop).
        for (int i = t; i < 64 * 32; i += 256) {
            int rr = i >> 5, c4 = i & 31;
            int r = r0 + rr;
            int b = r >> lg_nhalf;
            int iw = r - (b << lg_nhalf);
            long long base = (long long)b * (2 * n_half);
            float4 l4 = hin4[(base + 2 * iw) * 32 + c4];
            float4 r4 = hin4[(base + 2 * iw + 1) * 32 + c4];
            float xv[4] = {l4.x + r4.x, l4.y + r4.y, l4.z + r4.z, l4.w + r4.w};
            __nv_bfloat16 hi[4], lo[4];
#pragma unroll
            for (int j = 0; j < 4; j++) {
                hi[j] = __float2bfloat16_rn(xv[j]);
                lo[j] = __float2bfloat16_rn(xv[j] - __bfloat162float(hi[j]));
            }
            u32 sw = (u32)(2 * c4) ^ ((rr & 7) << 2);
            *(uint2*)(sm + (rr * 64 + sw) * 4) = *(uint2*)hi;
            *(uint2*)(sm + QB_ALO + (rr * 64 + sw) * 4) = *(uint2*)lo;
        }

        // Prefetch epilogue operands (latency drains behind the MMA loop).
        float2 hl_pre[2][2], hr_pre[2][2];
#pragma unroll
        for (int mf = 0; mf < 2; mf++)
#pragma unroll
            for (int half = 0; half < 2; half++) {
                int rr = wm * 32 + mf * 16 + grp + half * 8;
                int r = r0 + rr;
                int b = r >> lg_nhalf;
                int iw = r - (b << lg_nhalf);
                long long rowL = (long long)b * (2 * n_half) + 2 * iw;
                hl_pre[mf][half] = *(const float2*)&hin[rowL * 128 + hcol];
                hr_pre[mf][half] = *(const float2*)&hin[(rowL + 1) * 128 + hcol];
            }

        CP_WAIT0();  // B ready (no-op after first tile)
        __syncthreads();

        float acc[2][5][4];
#pragma unroll
        for (int a = 0; a < 2; a++)
#pragma unroll
            for (int g = 0; g < 5; g++)
#pragma unroll
                for (int c = 0; c < 4; c++) acc[a][g][c] = 0.0f;

#pragma unroll 1
        for (int ks = 0; ks < 8; ks++) {
#pragma unroll
            for (int split = 0; split < 3; split++) {
                u32 abase = smb + ((split == 2) ? (u32)QB_ALO : 0u);
                u32 bbase = smb + QB_B + ((split == 1) ? 40960u : 0u);
                u32 ka = (((u32)(ks * 8) + tka) ^ xsw) * 4;
                u32 kb = (((u32)(ks * 8) + tkb) ^ xsw) * 4;
                u32 af[2][4];
                ldsm4(af[0], abase + (u32)arow * 256 + ka);
                ldsm4(af[1], abase + (u32)(arow + 16) * 256 + ka);
                u32 b01[4], b23[4], b4[2];
                ldsm4(b01, bbase + (u32)((0 + bgsel) * 32 + rowB) * 256 + kb);
                ldsm4(b23, bbase + (u32)((2 + bgsel) * 32 + rowB) * 256 + kb);
                ldsm2(b4, bbase + (u32)(4 * 32 + rowB) * 256 + kb);
                mma16816(acc[0][0], af[0], b01[0], b01[1]);
                mma16816(acc[1][0], af[1], b01[0], b01[1]);
                mma16816(acc[0][1], af[0], b01[2], b01[3]);
                mma16816(acc[1][1], af[1], b01[2], b01[3]);
                mma16816(acc[0][2], af[0], b23[0], b23[1]);
                mma16816(acc[1][2], af[1], b23[0], b23[1]);
                mma16816(acc[0][3], af[0], b23[2], b23[3]);
                mma16816(acc[1][3], af[1], b23[2], b23[3]);
                mma16816(acc[0][4], af[0], b4[0], b4[1]);
                mma16816(acc[1][4], af[1], b4[0], b4[1]);
            }
        }

        // Epilogue: gates + hl/hr already in registers.
#pragma unroll
        for (int mf = 0; mf < 2; mf++) {
#pragma unroll
            for (int half = 0; half < 2; half++) {
                int rr = wm * 32 + mf * 16 + grp + half * 8;
                int r = r0 + rr;
                float hl2[2] = {hl_pre[mf][half].x, hl_pre[mf][half].y};
                float hr2[2] = {hr_pre[mf][half].x, hr_pre[mf][half].y};
                float ov[2];
#pragma unroll
                for (int j = 0; j < 2; j++) {
                    int e = half * 2 + j;
                    float si = acc[mf][0][e] + bias_s[0 * 32 + cl + j];
                    float sl = acc[mf][1][e] + bias_s[1 * 32 + cl + j];
                    float sr = acc[mf][2][e] + bias_s[2 * 32 + cl + j];
                    float so = acc[mf][3][e] + bias_s[3 * 32 + cl + j];
                    float sg = acc[mf][4][e] + bias_s[4 * 32 + cl + j];
                    float cc = sig_fast(si) * tanh_f(sg) + sig_fast(sl) * hl2[j] +
                               sig_fast(sr) * hr2[j];
                    ov[j] = sig_fast(so) * tanh_f(cc);
                }
                *(float2*)&hout[(long long)r * 128 + hcol] = make_float2(ov[0], ov[1]);
            }
        }
    }
}

// ---------------- launcher ----------------
extern "C" void kernel_launch(void* const* d_in, const int* in_sizes, int n_in,
                              void* d_out, int out_size) {
    const int* ids = (const int*)d_in[0];
    const float* emb = (const float*)d_in[1];
    const float* Wwh = (const float*)d_in[2];
    const float* Whh = (const float*)d_in[3];
    const float* bhh = (const float*)d_in[4];
    float* out = (float*)d_out;

    const int smem_embed = 98304;
    cudaFuncSetAttribute(embed_pers, cudaFuncAttributeMaxDynamicSharedMemorySize, smem_embed);
    cudaFuncSetAttribute(combine_q, cudaFuncAttributeMaxDynamicSharedMemorySize, QB_SM);

    prep_both<<<(128 * 640 + 128 * 128 + 255) / 256, 256>>>(Whh, Wwh);

    {
        int ntiles = (BB_ * LL_) / 64;  // 2048
        int gx = ntiles < 296 ? ntiles : 296;
        embed_pers<<<gx, 256, smem_embed>>>(ids, emb, ntiles);
    }

    for (int tlev = 1; tlev <= 11; ++tlev) {
        int ntiles = (BB_ * (LL_ >> tlev)) / 64;  // M=64 tiles
        int lg = 11 - tlev;
        int src_sel = (tlev & 1) ? 0 : 1;
        int dst_sel = (tlev == 11) ? 2 : ((tlev & 1) ? 1 : 0);
        int gx = ntiles < 74 ? ntiles : 74;
        dim3 grid(gx, 4);
        combine_q<<<grid, 256, QB_SM>>>(src_sel, out, dst_sel, bhh, lg, ntiles);
    }
}